// round 4
// baseline (speedup 1.0000x reference)
#include <cuda_runtime.h>

// Hopf oscillator scan — R4: scalar layout, 1 channel/thread.
// Trend: occ 20%->40% moved DRAM 66%->70%. The recurrence's serial
// sincos+FMA chain leaves each warp latency-exposed; the fix is raw warp
// count. 262144 threads => ~55 warps/SM (occ ~80%), 1 sincos/iter/thread,
// ~30 regs. Loads/stores stay fully coalesced (128B per warp op).

#define HOPF_DT      0.01f
#define HOPF_SCALER  20.0f

static constexpr int BS  = 8;
static constexpr int T   = 64;
static constexpr int CPB = 32 * 32 * 32;   // channels per batch = 32768
static constexpr int PF  = 4;              // prefetch ring depth (power of 2)

__device__ __forceinline__ float ldcs1(const float* p) {
    float v;
    asm volatile("ld.global.cs.f32 %0, [%1];" : "=f"(v) : "l"(p));
    return v;
}

__device__ __forceinline__ void stcs1(float* p, float v) {
    asm volatile("st.global.cs.f32 [%0], %1;" :: "l"(p), "f"(v) : "memory");
}

__global__ __launch_bounds__(256)
void hopf_scan_kernel(const float* __restrict__ Xr,
                      const float* __restrict__ Xi,
                      const float* __restrict__ Om,
                      float* __restrict__ OutR,
                      float* __restrict__ OutI)
{
    const int u = blockIdx.x * blockDim.x + threadIdx.x;  // 0..262143
    const int b = u >> 15;            // / CPB
    const int c = u & (CPB - 1);      // % CPB

    const float om = Om[c];

    float r = 1.0f, phi = 0.0f, cs = 1.0f, sn = 0.0f;

    const int base = (b * T) * CPB + c;

    // Preload stages t = 0..PF-2
    float xrb[PF], xib[PF];
#pragma unroll
    for (int p = 0; p < PF - 1; ++p) {
        xrb[p] = ldcs1(Xr + base + p * CPB);
        xib[p] = ldcs1(Xi + base + p * CPB);
    }

#pragma unroll 4
    for (int t = 0; t < T; ++t) {
        // Prefetch t+PF-1 into its ring slot (clamped at the tail).
        {
            const int tp   = t + PF - 1;
            const int offp = base + ((tp < T) ? tp : (T - 1)) * CPB;
            xrb[tp & (PF - 1)] = ldcs1(Xr + offp);
            xib[tp & (PF - 1)] = ldcs1(Xi + offp);
        }

        const float xr = xrb[t & (PF - 1)];
        const float xi = xib[t & (PF - 1)];

        const float input_r   = HOPF_SCALER * xr * cs;
        const float input_phi = HOPF_SCALER * xi * sn;
        r   = r + ((1.0f - r * r) * r + input_r) * HOPF_DT;
        phi = phi + (om - input_phi) * HOPF_DT;
        __sincosf(phi, &sn, &cs);

        const int off = base + t * CPB;
        stcs1(OutR + off, r * cs);
        stcs1(OutI + off, r * sn);
    }
}

extern "C" void kernel_launch(void* const* d_in, const int* in_sizes, int n_in,
                              void* d_out, int out_size)
{
    const float* Xr = (const float*)d_in[0];
    const float* Xi = (const float*)d_in[1];
    const float* Om = (const float*)d_in[2];

    float* out  = (float*)d_out;
    const int n_elem = BS * T * CPB;            // 16,777,216 per output tensor
    float* OutR = out;
    float* OutI = out + n_elem;

    const int n_threads = BS * CPB;             // 262144
    hopf_scan_kernel<<<n_threads / 256, 256>>>(Xr, Xi, Om, OutR, OutI);
}

// round 5
// speedup vs baseline: 1.0341x; 1.0341x over previous
#include <cuda_runtime.h>

// Hopf oscillator scan — R5: scalar layout + PF=8 deep prefetch +
// clamp-free main loop (epilogue handles the tail), unroll 8.
// R4 established: grid-limited occ (56 warps/SM), DRAM ~71%, plateau.
// This round removes per-iter clamp ALU and deepens MLP at high occupancy.

#define HOPF_DT      0.01f
#define HOPF_SCALER  20.0f

static constexpr int BS  = 8;
static constexpr int T   = 64;
static constexpr int CPB = 32 * 32 * 32;   // channels per batch = 32768
static constexpr int PF  = 8;              // prefetch ring depth (power of 2)

__device__ __forceinline__ float ldcs1(const float* p) {
    float v;
    asm volatile("ld.global.cs.f32 %0, [%1];" : "=f"(v) : "l"(p));
    return v;
}

__device__ __forceinline__ void stcs1(float* p, float v) {
    asm volatile("st.global.cs.f32 [%0], %1;" :: "l"(p), "f"(v) : "memory");
}

__global__ __launch_bounds__(256)
void hopf_scan_kernel(const float* __restrict__ Xr,
                      const float* __restrict__ Xi,
                      const float* __restrict__ Om,
                      float* __restrict__ OutR,
                      float* __restrict__ OutI)
{
    const int u = blockIdx.x * blockDim.x + threadIdx.x;  // 0..262143
    const int b = u >> 15;            // / CPB
    const int c = u & (CPB - 1);      // % CPB

    const float om = Om[c];

    float r = 1.0f, phi = 0.0f, cs = 1.0f, sn = 0.0f;

    const int base = (b * T) * CPB + c;

    // Preload stages t = 0..PF-2
    float xrb[PF], xib[PF];
#pragma unroll
    for (int p = 0; p < PF - 1; ++p) {
        xrb[p] = ldcs1(Xr + base + p * CPB);
        xib[p] = ldcs1(Xi + base + p * CPB);
    }

    // Main loop: prefetch of t+PF-1 is always in-bounds (t <= T-PF).
#pragma unroll 8
    for (int t = 0; t < T - (PF - 1); ++t) {
        const int tp = t + PF - 1;
        xrb[tp & (PF - 1)] = ldcs1(Xr + base + tp * CPB);
        xib[tp & (PF - 1)] = ldcs1(Xi + base + tp * CPB);

        const float xr = xrb[t & (PF - 1)];
        const float xi = xib[t & (PF - 1)];

        const float input_r   = HOPF_SCALER * xr * cs;
        const float input_phi = HOPF_SCALER * xi * sn;
        r   = r + ((1.0f - r * r) * r + input_r) * HOPF_DT;
        phi = phi + (om - input_phi) * HOPF_DT;
        __sincosf(phi, &sn, &cs);

        const int off = base + t * CPB;
        stcs1(OutR + off, r * cs);
        stcs1(OutI + off, r * sn);
    }

    // Epilogue: last PF-1 iterations, all data already resident in the ring.
#pragma unroll
    for (int t = T - (PF - 1); t < T; ++t) {
        const float xr = xrb[t & (PF - 1)];
        const float xi = xib[t & (PF - 1)];

        const float input_r   = HOPF_SCALER * xr * cs;
        const float input_phi = HOPF_SCALER * xi * sn;
        r   = r + ((1.0f - r * r) * r + input_r) * HOPF_DT;
        phi = phi + (om - input_phi) * HOPF_DT;
        __sincosf(phi, &sn, &cs);

        const int off = base + t * CPB;
        stcs1(OutR + off, r * cs);
        stcs1(OutI + off, r * sn);
    }
}

extern "C" void kernel_launch(void* const* d_in, const int* in_sizes, int n_in,
                              void* d_out, int out_size)
{
    const float* Xr = (const float*)d_in[0];
    const float* Xi = (const float*)d_in[1];
    const float* Om = (const float*)d_in[2];

    float* out  = (float*)d_out;
    const int n_elem = BS * T * CPB;            // 16,777,216 per output tensor
    float* OutR = out;
    float* OutI = out + n_elem;

    const int n_threads = BS * CPB;             // 262144
    hopf_scan_kernel<<<n_threads / 256, 256>>>(Xr, Xi, Om, OutR, OutI);
}